// round 1
// baseline (speedup 1.0000x reference)
#include <cuda_runtime.h>
#include <math.h>

// Problem constants (fixed shapes for this problem instance)
#define NNODE 10000
#define CCH   128
#define NEDGE 320000
#define NGR   8
#define NPER  1250      // NNODE / NGR
#define KTOP  1000      // ceil(0.8 * 1250)
#define NK    8000      // NGR * KTOP

// Output layout (f32 concat of [x_p, new_edge_index, new_attr, batch_p])
#define OFF1  (NK * CCH)                 // 1,024,000  end of x_p
#define E2    (NK * KTOP)                // 8,000,000  edges after pooling
#define OFF2  (OFF1 + E2)                // 9,024,000  end of nrow
#define OFF3  (OFF2 + E2)                // 17,024,000 end of ncol
#define OFF4  (OFF3 + E2)                // 25,024,000 end of attr
#define TOTAL (OFF4 + NK)                // 25,032,000

// ---------------- scratch (static device globals; no allocation) -------------
__device__ int   g_deg[NNODE];
__device__ int   g_cnt[NNODE];
__device__ int   g_rowptr[NNODE + 1];
__device__ int   g_cursor[NNODE];
__device__ int   g_src[NEDGE];
__device__ float g_dis[NNODE];
__device__ float g_s[NNODE];
__device__ int   g_perm[NK];
__device__ float g_a;

// ---------------- kernels ----------------------------------------------------

// zero counters + compute a = sum(w)/sqrt(sum(w*w))
__global__ void k_init(const float* __restrict__ w) {
    int i = blockIdx.x * blockDim.x + threadIdx.x;
    if (i < NNODE) { g_deg[i] = 0; g_cnt[i] = 0; }
    if (blockIdx.x == 0 && threadIdx.x < 32) {
        float sw = 0.f, sw2 = 0.f;
        for (int c = threadIdx.x; c < CCH; c += 32) {
            float v = w[c];
            sw += v; sw2 += v * v;
        }
        for (int o = 16; o; o >>= 1) {
            sw  += __shfl_xor_sync(0xFFFFFFFFu, sw, o);
            sw2 += __shfl_xor_sync(0xFFFFFFFFu, sw2, o);
        }
        if (threadIdx.x == 0) g_a = sw / sqrtf(sw2);
    }
}

// out-degree (by src) for normalization, in-degree (by dst) for CSR
__global__ void k_deg(const int* __restrict__ row, const int* __restrict__ col) {
    int i = blockIdx.x * blockDim.x + threadIdx.x;
    if (i < NEDGE) {
        atomicAdd(&g_deg[row[i]], 1);
        atomicAdd(&g_cnt[col[i]], 1);
    }
}

__global__ void k_dis() {
    int i = blockIdx.x * blockDim.x + threadIdx.x;
    if (i < NNODE) {
        int d = g_deg[i];
        g_dis[i] = (d > 0) ? (1.0f / sqrtf((float)d)) : 0.0f;
    }
}

// exclusive scan of g_cnt -> g_rowptr (+ cursor copy). single block, 1024 thr.
__global__ void k_scan() {
    __shared__ int sh[1024];
    int tid = threadIdx.x;
    int carry = 0;
    for (int base = 0; base < NNODE; base += 1024) {
        int idx = base + tid;
        int v = (idx < NNODE) ? g_cnt[idx] : 0;
        sh[tid] = v;
        __syncthreads();
        for (int off = 1; off < 1024; off <<= 1) {
            int t = (tid >= off) ? sh[tid - off] : 0;
            __syncthreads();
            sh[tid] += t;
            __syncthreads();
        }
        int excl = carry + sh[tid] - v;
        if (idx < NNODE) { g_rowptr[idx] = excl; g_cursor[idx] = excl; }
        carry += sh[1023];
        __syncthreads();
    }
    if (tid == 0) g_rowptr[NNODE] = carry;
}

// scatter edges into CSR by dst
__global__ void k_scatter(const int* __restrict__ row, const int* __restrict__ col) {
    int i = blockIdx.x * blockDim.x + threadIdx.x;
    if (i < NEDGE) {
        int d = col[i];
        int p = atomicAdd(&g_cursor[d], 1);
        g_src[p] = row[i];
    }
}

// one block (128 threads) per dst node: gather neighbor sum, score, s=tanh
__global__ void k_score(const float* __restrict__ x) {
    __shared__ int   s_src[128];
    __shared__ float s_coef[128];
    __shared__ float red[128];
    int j = blockIdx.x;
    int c = threadIdx.x;
    int st = g_rowptr[j], en = g_rowptr[j + 1];
    float dj = g_dis[j];
    float acc = 0.f;
    for (int base = st; base < en; base += 128) {
        int idx = base + c;
        __syncthreads();
        if (idx < en) {
            int s = g_src[idx];
            s_src[c] = s;
            s_coef[c] = g_dis[s];
        }
        __syncthreads();
        int cnt = min(128, en - base);
        for (int t = 0; t < cnt; t++)
            acc += s_coef[t] * x[s_src[t] * CCH + c];
    }
    float info = x[j * CCH + c] - dj * acc;
    red[c] = fabsf(info);
    __syncthreads();
    for (int off = 64; off > 0; off >>= 1) {
        if (c < off) red[c] += red[c + off];
        __syncthreads();
    }
    if (c == 0) g_s[j] = tanhf(red[0] * g_a);
}

// per-graph stable top-k via bitonic sort on composite key (s desc, idx asc)
__global__ void k_sort() {
    __shared__ unsigned long long key[2048];
    int g = blockIdx.x;
    int tid = threadIdx.x;
    for (int i = tid; i < 2048; i += 1024) {
        unsigned long long kk;
        if (i < NPER) {
            float v = g_s[g * NPER + i];
            unsigned u = __float_as_uint(v);
            u ^= (u & 0x80000000u) ? 0xFFFFFFFFu : 0x80000000u;  // order-preserving flip
            kk = (((unsigned long long)(~u)) << 32) | (unsigned)i; // s desc, idx asc
        } else {
            kk = 0xFFFFFFFFFFFFFFFFull;                            // pad sorts last
        }
        key[i] = kk;
    }
    __syncthreads();
    for (int k2 = 2; k2 <= 2048; k2 <<= 1) {
        for (int j = k2 >> 1; j > 0; j >>= 1) {
            for (int i = tid; i < 2048; i += 1024) {
                int ixj = i ^ j;
                if (ixj > i) {
                    bool asc = ((i & k2) == 0);
                    unsigned long long a = key[i], b = key[ixj];
                    if ((a > b) == asc) { key[i] = b; key[ixj] = a; }
                }
            }
            __syncthreads();
        }
    }
    if (tid < KTOP) {
        int idx = (int)(key[tid] & 0xFFFFFFFFull);
        g_perm[g * KTOP + tid] = g * NPER + idx;
    }
}

__device__ __forceinline__ float out_value(int t, const float* __restrict__ x) {
    if (t < OFF1) {
        int i = t >> 7, c = t & 127;
        int p = g_perm[i];
        return x[p * CCH + c] * g_s[p];
    } else if (t < OFF2) {
        return (float)((t - OFF1) / KTOP);
    } else if (t < OFF3) {
        int u = t - OFF2;
        return (float)((u / (KTOP * KTOP)) * KTOP + u % KTOP);
    } else if (t < OFF4) {
        return 1.0f;
    } else if (t < TOTAL) {
        return (float)((t - OFF4) / KTOP);
    }
    return 0.0f;
}

// vectorized output writer (n must be multiple of 4)
__global__ void k_out4(const float* __restrict__ x, float4* __restrict__ out, int n4) {
    int j4 = blockIdx.x * blockDim.x + threadIdx.x;
    if (j4 >= n4) return;
    int j = j4 * 4;
    float4 v;
    v.x = out_value(j + 0, x);
    v.y = out_value(j + 1, x);
    v.z = out_value(j + 2, x);
    v.w = out_value(j + 3, x);
    out[j4] = v;
}

__global__ void k_out1(const float* __restrict__ x, float* __restrict__ out, int n) {
    int j = blockIdx.x * blockDim.x + threadIdx.x;
    if (j < n) out[j] = out_value(j, x);
}

// ---------------- launch ------------------------------------------------------
extern "C" void kernel_launch(void* const* d_in, const int* in_sizes, int n_in,
                              void* d_out, int out_size) {
    const float* x  = (const float*)d_in[0];
    const int*   ei = (const int*)d_in[1];
    const float* w  = (const float*)d_in[4];   // topk_weight
    float* out = (float*)d_out;

    const int* row = ei;            // edge_index[0]
    const int* col = ei + NEDGE;    // edge_index[1]

    k_init<<<(NNODE + 255) / 256, 256>>>(w);
    k_deg<<<(NEDGE + 255) / 256, 256>>>(row, col);
    k_dis<<<(NNODE + 255) / 256, 256>>>();
    k_scan<<<1, 1024>>>();
    k_scatter<<<(NEDGE + 255) / 256, 256>>>(row, col);
    k_score<<<NNODE, 128>>>(x);
    k_sort<<<NGR, 1024>>>();

    if ((out_size & 3) == 0) {
        int n4 = out_size / 4;
        k_out4<<<(n4 + 255) / 256, 256>>>(x, (float4*)out, n4);
    } else {
        k_out1<<<(out_size + 255) / 256, 256>>>(x, out, out_size);
    }
}

// round 2
// speedup vs baseline: 1.0833x; 1.0833x over previous
#include <cuda_runtime.h>
#include <math.h>

// Problem constants (fixed shapes for this problem instance)
#define NNODE 10000
#define CCH   128
#define NEDGE 320000
#define NGR   8
#define NPER  1250
#define KTOP  1000
#define NK    8000      // NGR * KTOP

// Output layout (f32 concat of [x_p, new_edge_index(2 rows), new_attr, batch_p])
#define OFF1  (NK * CCH)                 // 1,024,000
#define E2    (NK * KTOP)                // 8,000,000
#define OFF2  (OFF1 + E2)                // 9,024,000
#define OFF3  (OFF2 + E2)                // 17,024,000
#define OFF4  (OFF3 + E2)                // 25,024,000
#define TOTAL (OFF4 + NK)                // 25,032,000
#define F_TOTAL (TOTAL / 4)              // 6,258,000 float4s

// f4-index slice boundaries for the constant-fill region [OFF1/4, F_TOTAL)
#define S_XP_END   256000                // OFF1/4
#define S_DEG_END  1456000
#define S_SCAN_END 2856000
#define S_SCAT_END 4056000
#define S_SCORE_END 5156000
#define S_SORT_END 6056000
// final kernel: [S_SORT_END, F_TOTAL) + x_p [0, S_XP_END)

// fill-block counts per kernel
#define FB_DEG   1024
#define FB_SCAN  256
#define FB_SCAT  1024
#define FB_SCORE 2048
#define FB_SORT  256

// ---------------- scratch -----------------------------------------------------
__device__ int   g_deg[NNODE];
__device__ int   g_cnt[NNODE];
__device__ int   g_rowptr[NNODE + 1];
__device__ int   g_cursor[NNODE];
__device__ int   g_src[NEDGE];
__device__ float g_dis[NNODE];
__device__ float g_s[NNODE];
__device__ int   g_perm[NK];
__device__ float g_a;

// ---------------- output value generation -------------------------------------
__device__ __forceinline__ void write_f4(float4* __restrict__ out, int j4,
                                         const float* __restrict__ x) {
    int t = j4 << 2;
    float4 v;
    if (t < OFF1) {                       // x_p  (only used by final kernel)
        int i = t >> 7;
        int p = g_perm[i];
        float s = g_s[p];
        float4 xv = ((const float4*)(x + p * CCH))[(t & 127) >> 2];
        v.x = xv.x * s; v.y = xv.y * s; v.z = xv.z * s; v.w = xv.w * s;
    } else if (t < OFF2) {                // nrow = u/1000 (constant within f4)
        float f = (float)((t - OFF1) / KTOP);
        v = make_float4(f, f, f, f);
    } else if (t < OFF3) {                // ncol = (u/1e6)*1000 + u%1000
        int u = t - OFF2;
        int b = (u / (KTOP * KTOP)) * KTOP + u % KTOP;
        v = make_float4((float)b, (float)(b + 1), (float)(b + 2), (float)(b + 3));
    } else if (t < OFF4) {                // attr = 1
        v = make_float4(1.f, 1.f, 1.f, 1.f);
    } else {                              // batch_p = u/1000
        float f = (float)((t - OFF4) / KTOP);
        v = make_float4(f, f, f, f);
    }
    out[j4] = v;
}

__device__ __forceinline__ void fill_range(float4* __restrict__ out,
                                           const float* __restrict__ x,
                                           int lo, int hi, int fb, int nfb,
                                           int tid, int bsz) {
    int idx = lo + fb * bsz + tid;
    int stride = nfb * bsz;
    for (; idx < hi; idx += stride) write_f4(out, idx, x);
}

// ---------------- kernels ------------------------------------------------------

__global__ void k_init(const float* __restrict__ w) {
    int i = blockIdx.x * blockDim.x + threadIdx.x;
    if (i < NNODE) { g_deg[i] = 0; g_cnt[i] = 0; }
    if (blockIdx.x == 0 && threadIdx.x < 32) {
        float sw = 0.f, sw2 = 0.f;
        for (int c = threadIdx.x; c < CCH; c += 32) {
            float v = w[c];
            sw += v; sw2 += v * v;
        }
        for (int o = 16; o; o >>= 1) {
            sw  += __shfl_xor_sync(0xFFFFFFFFu, sw, o);
            sw2 += __shfl_xor_sync(0xFFFFFFFFu, sw2, o);
        }
        if (threadIdx.x == 0) g_a = sw / sqrtf(sw2);
    }
}

__global__ void k_deg(const int* __restrict__ row, const int* __restrict__ col,
                      float4* __restrict__ out, const float* __restrict__ x) {
    int b = blockIdx.x;
    if (b < NEDGE / 256) {
        int i = b * 256 + threadIdx.x;
        atomicAdd(&g_deg[row[i]], 1);
        atomicAdd(&g_cnt[col[i]], 1);
    } else {
        fill_range(out, x, S_XP_END, S_DEG_END, b - NEDGE / 256, FB_DEG,
                   threadIdx.x, 256);
    }
}

// single-pass scan (block 0) + dis computation; other blocks fill
__global__ void k_scan(float4* __restrict__ out, const float* __restrict__ x) {
    if (blockIdx.x == 0) {
        int tid = threadIdx.x;
        int base = tid * 10;
        int loc[10];
        int sum = 0;
        bool act = (base < NNODE);
        if (act) {
#pragma unroll
            for (int q = 0; q < 10; q++) { int v = g_cnt[base + q]; loc[q] = v; sum += v; }
        }
        int lane = tid & 31, wid = tid >> 5;
        int val = sum;
#pragma unroll
        for (int o = 1; o < 32; o <<= 1) {
            int n = __shfl_up_sync(0xFFFFFFFFu, val, o);
            if (lane >= o) val += n;
        }
        __shared__ int wsum[32];
        if (lane == 31) wsum[wid] = val;
        __syncthreads();
        if (wid == 0) {
            int v2 = wsum[lane];
#pragma unroll
            for (int o = 1; o < 32; o <<= 1) {
                int n = __shfl_up_sync(0xFFFFFFFFu, v2, o);
                if (lane >= o) v2 += n;
            }
            wsum[lane] = v2;
        }
        __syncthreads();
        int excl = val - sum + (wid > 0 ? wsum[wid - 1] : 0);
        if (act) {
#pragma unroll
            for (int q = 0; q < 10; q++) {
                int n = base + q;
                g_rowptr[n] = excl; g_cursor[n] = excl; excl += loc[q];
                int d = g_deg[n];
                g_dis[n] = (d > 0) ? (1.0f / sqrtf((float)d)) : 0.0f;
            }
        }
        if (tid == 1023) g_rowptr[NNODE] = wsum[31];
    } else {
        fill_range(out, x, S_DEG_END, S_SCAN_END, blockIdx.x - 1, FB_SCAN,
                   threadIdx.x, 1024);
    }
}

__global__ void k_scatter(const int* __restrict__ row, const int* __restrict__ col,
                          float4* __restrict__ out, const float* __restrict__ x) {
    int b = blockIdx.x;
    if (b < NEDGE / 256) {
        int i = b * 256 + threadIdx.x;
        int d = col[i];
        int p = atomicAdd(&g_cursor[d], 1);
        g_src[p] = row[i];
    } else {
        fill_range(out, x, S_SCAN_END, S_SCAT_END, b - NEDGE / 256, FB_SCAT,
                   threadIdx.x, 256);
    }
}

__global__ void k_score(const float* __restrict__ x, float4* __restrict__ out) {
    int b = blockIdx.x;
    if (b < NNODE) {
        __shared__ int   s_off[128];
        __shared__ float s_coef[128];
        __shared__ float wred[4];
        int c = threadIdx.x;
        int st = g_rowptr[b], en = g_rowptr[b + 1];
        float acc0 = 0.f, acc1 = 0.f, acc2 = 0.f, acc3 = 0.f;
        for (int base = st; base < en; base += 128) {
            __syncthreads();
            int idx = base + c;
            if (idx < en) {
                int s = g_src[idx];
                s_off[c] = s * CCH;
                s_coef[c] = g_dis[s];
            }
            __syncthreads();
            int cnt = min(128, en - base);
            int t = 0;
            for (; t + 4 <= cnt; t += 4) {
                acc0 += s_coef[t]     * x[s_off[t]     + c];
                acc1 += s_coef[t + 1] * x[s_off[t + 1] + c];
                acc2 += s_coef[t + 2] * x[s_off[t + 2] + c];
                acc3 += s_coef[t + 3] * x[s_off[t + 3] + c];
            }
            for (; t < cnt; t++) acc0 += s_coef[t] * x[s_off[t] + c];
        }
        float acc = (acc0 + acc1) + (acc2 + acc3);
        float info = x[b * CCH + c] - g_dis[b] * acc;
        float v = fabsf(info);
#pragma unroll
        for (int o = 16; o; o >>= 1) v += __shfl_xor_sync(0xFFFFFFFFu, v, o);
        if ((c & 31) == 0) wred[c >> 5] = v;
        __syncthreads();
        if (c == 0) g_s[b] = tanhf((wred[0] + wred[1] + wred[2] + wred[3]) * g_a);
    } else {
        fill_range(out, x, S_SCAT_END, S_SCORE_END, b - NNODE, FB_SCORE,
                   threadIdx.x, 128);
    }
}

// per-graph stable top-k (bitonic on composite key: s desc, idx asc)
__global__ void k_sort(float4* __restrict__ out, const float* __restrict__ x) {
    int b = blockIdx.x;
    if (b < NGR) {
        __shared__ unsigned long long key[2048];
        int g = b;
        int tid = threadIdx.x;
        for (int i = tid; i < 2048; i += 1024) {
            unsigned long long kk;
            if (i < NPER) {
                unsigned u = __float_as_uint(g_s[g * NPER + i]);
                u ^= (u & 0x80000000u) ? 0xFFFFFFFFu : 0x80000000u;
                kk = (((unsigned long long)(~u)) << 32) | (unsigned)i;
            } else {
                kk = 0xFFFFFFFFFFFFFFFFull;
            }
            key[i] = kk;
        }
        __syncthreads();
        for (int k2 = 2; k2 <= 2048; k2 <<= 1) {
            for (int j = k2 >> 1; j > 0; j >>= 1) {
                for (int i = tid; i < 2048; i += 1024) {
                    int ixj = i ^ j;
                    if (ixj > i) {
                        bool asc = ((i & k2) == 0);
                        unsigned long long a = key[i], bb = key[ixj];
                        if ((a > bb) == asc) { key[i] = bb; key[ixj] = a; }
                    }
                }
                __syncthreads();
            }
        }
        if (tid < KTOP) {
            int idx = (int)(key[tid] & 0xFFFFFFFFull);
            g_perm[g * KTOP + tid] = g * NPER + idx;
        }
    } else {
        fill_range(out, x, S_SCORE_END, S_SORT_END, b - NGR, FB_SORT,
                   threadIdx.x, 1024);
    }
}

// final: x_p gather + remaining constant tail
#define FIN_N (S_XP_END + (F_TOTAL - S_SORT_END))   // 458,000 f4
__global__ void k_final(const float* __restrict__ x, float4* __restrict__ out) {
    int l = blockIdx.x * 256 + threadIdx.x;
    if (l >= FIN_N) return;
    int j4 = (l < S_XP_END) ? l : l + (S_SORT_END - S_XP_END);
    write_f4(out, j4, x);
}

// generic fallback (scalar) if out_size != TOTAL
__device__ __forceinline__ float out_value1(int t, const float* __restrict__ x) {
    if (t < OFF1) {
        int i = t >> 7, c = t & 127;
        int p = g_perm[i];
        return x[p * CCH + c] * g_s[p];
    } else if (t < OFF2) return (float)((t - OFF1) / KTOP);
    else if (t < OFF3) {
        int u = t - OFF2;
        return (float)((u / (KTOP * KTOP)) * KTOP + u % KTOP);
    } else if (t < OFF4) return 1.0f;
    else if (t < TOTAL) return (float)((t - OFF4) / KTOP);
    return 0.0f;
}
__global__ void k_out1(const float* __restrict__ x, float* __restrict__ out, int n) {
    int j = blockIdx.x * blockDim.x + threadIdx.x;
    if (j < n) out[j] = out_value1(j, x);
}

// ---------------- launch ------------------------------------------------------
extern "C" void kernel_launch(void* const* d_in, const int* in_sizes, int n_in,
                              void* d_out, int out_size) {
    const float* x  = (const float*)d_in[0];
    const int*   ei = (const int*)d_in[1];
    const float* w  = (const float*)d_in[4];   // topk_weight
    float4* out = (float4*)d_out;

    const int* row = ei;
    const int* col = ei + NEDGE;

    bool fused = (out_size == TOTAL);

    k_init<<<(NNODE + 255) / 256, 256>>>(w);
    if (fused) {
        k_deg    <<<NEDGE / 256 + FB_DEG,  256>>>(row, col, out, x);
        k_scan   <<<1 + FB_SCAN,          1024>>>(out, x);
        k_scatter<<<NEDGE / 256 + FB_SCAT, 256>>>(row, col, out, x);
        k_score  <<<NNODE + FB_SCORE,      128>>>(x, out);
        k_sort   <<<NGR + FB_SORT,        1024>>>(out, x);
        k_final  <<<(FIN_N + 255) / 256,   256>>>(x, out);
    } else {
        k_deg    <<<NEDGE / 256, 256>>>(row, col, out, x);
        k_scan   <<<1, 1024>>>(out, x);
        k_scatter<<<NEDGE / 256, 256>>>(row, col, out, x);
        k_score  <<<NNODE, 128>>>(x, out);
        k_sort   <<<NGR, 1024>>>(out, x);
        k_out1   <<<(out_size + 255) / 256, 256>>>(x, (float*)d_out, out_size);
    }
}

// round 3
// speedup vs baseline: 1.1087x; 1.0234x over previous
#include <cuda_runtime.h>
#include <math.h>

// Problem constants
#define NNODE 10000
#define CCH   128
#define NEDGE 320000
#define NGR   8
#define NPER  1250
#define KTOP  1000
#define NK    8000

// element-space layout
#define OFF1  (NK * CCH)                 // 1,024,000
#define E2    (NK * KTOP)                // 8,000,000
#define OFF2  (OFF1 + E2)
#define OFF3  (OFF2 + E2)
#define OFF4  (OFF3 + E2)
#define TOTAL (OFF4 + NK)                // 25,032,000

// float4-space region starts
#define R_XP    0u
#define R_NROW  256000u
#define R_NCOL  2256000u
#define R_ATTR  4256000u
#define R_BATCH 6256000u
#define F_TOTAL 6258000u

// ---------------- scratch -----------------------------------------------------
__device__ int   g_deg[NNODE];
__device__ int   g_cnt[NNODE];
__device__ int   g_rowptr[NNODE + 1];
__device__ int   g_cursor[NNODE];
__device__ int   g_src[NEDGE];
__device__ float g_dis[NNODE];
__device__ float g_s[NNODE];
__device__ int   g_perm[NK];
__device__ float g_a;

// ---------------- division-free warp-period fills ------------------------------
// nrow region: period p (250 f4) all equal to (float)p.  p in [0,8000)
__device__ __forceinline__ void fill_nrow_p(float4* __restrict__ out,
                                            unsigned p0, unsigned p1,
                                            unsigned w, unsigned nw, unsigned lane) {
    for (unsigned p = p0 + w; p < p1; p += nw) {
        float4* base = out + R_NROW + p * 250u;
        float f = (float)p;
        float4 v = make_float4(f, f, f, f);
        for (unsigned i = lane; i < 250u; i += 32u) base[i] = v;
    }
}
// ncol region: period p -> values (g*1000 + 4i .. +3), g = p/1000
__device__ __forceinline__ void fill_ncol_p(float4* __restrict__ out,
                                            unsigned p0, unsigned p1,
                                            unsigned w, unsigned nw, unsigned lane) {
    for (unsigned p = p0 + w; p < p1; p += nw) {
        float4* base = out + R_NCOL + p * 250u;
        float g1000 = (float)((p / 1000u) * 1000u);
        float fb = g1000 + (float)(4u * lane);
        for (unsigned i = lane; i < 250u; i += 32u) {
            base[i] = make_float4(fb, fb + 1.f, fb + 2.f, fb + 3.f);
            fb += 128.f;
        }
    }
}
// attr region: flat ones
__device__ __forceinline__ void fill_attr_f(float4* __restrict__ out,
                                            unsigned lo, unsigned hi,
                                            unsigned t, unsigned nt) {
    float4 v = make_float4(1.f, 1.f, 1.f, 1.f);
    for (unsigned j = lo + t; j < hi; j += nt) out[j] = v;
}

// ---------------- kernels ------------------------------------------------------

// zero counters + a = sum(w)/sqrt(sum(w*w)); fill blocks: attr slice
__global__ void k_init(const float* __restrict__ w, float4* __restrict__ out,
                       unsigned alo, unsigned ahi) {
    int b = blockIdx.x;
    if (b < 40) {
        int i = b * 256 + threadIdx.x;
        if (i < NNODE) { g_deg[i] = 0; g_cnt[i] = 0; }
        if (b == 0 && threadIdx.x < 32) {
            float sw = 0.f, sw2 = 0.f;
            for (int c = threadIdx.x; c < CCH; c += 32) {
                float v = w[c]; sw += v; sw2 += v * v;
            }
            for (int o = 16; o; o >>= 1) {
                sw  += __shfl_xor_sync(0xFFFFFFFFu, sw, o);
                sw2 += __shfl_xor_sync(0xFFFFFFFFu, sw2, o);
            }
            if (threadIdx.x == 0) g_a = sw / sqrtf(sw2);
        }
    } else {
        unsigned nt = (gridDim.x - 40) * 256u;
        fill_attr_f(out, alo, ahi, (b - 40) * 256u + threadIdx.x, nt);
    }
}

__global__ void k_deg(const int* __restrict__ row, const int* __restrict__ col,
                      float4* __restrict__ out, unsigned alo, unsigned ahi) {
    int b = blockIdx.x;
    if (b < NEDGE / 256) {
        int i = b * 256 + threadIdx.x;
        atomicAdd(&g_deg[row[i]], 1);
        atomicAdd(&g_cnt[col[i]], 1);
    } else {
        unsigned nt = (gridDim.x - NEDGE / 256) * 256u;
        fill_attr_f(out, alo, ahi, (b - NEDGE / 256) * 256u + threadIdx.x, nt);
    }
}

// block 0: single-pass scan of cnt -> rowptr/cursor + dis; others: ncol fill
__global__ void k_scan(float4* __restrict__ out, unsigned np0, unsigned np1) {
    if (blockIdx.x == 0) {
        int tid = threadIdx.x;
        int base = tid * 10;
        int loc[10];
        int sum = 0;
        bool act = (base < NNODE);
        if (act) {
#pragma unroll
            for (int q = 0; q < 10; q++) { int v = g_cnt[base + q]; loc[q] = v; sum += v; }
        }
        int lane = tid & 31, wid = tid >> 5;
        int val = sum;
#pragma unroll
        for (int o = 1; o < 32; o <<= 1) {
            int n = __shfl_up_sync(0xFFFFFFFFu, val, o);
            if (lane >= o) val += n;
        }
        __shared__ int wsum[32];
        if (lane == 31) wsum[wid] = val;
        __syncthreads();
        if (wid == 0) {
            int v2 = wsum[lane];
#pragma unroll
            for (int o = 1; o < 32; o <<= 1) {
                int n = __shfl_up_sync(0xFFFFFFFFu, v2, o);
                if (lane >= o) v2 += n;
            }
            wsum[lane] = v2;
        }
        __syncthreads();
        int excl = val - sum + (wid > 0 ? wsum[wid - 1] : 0);
        if (act) {
#pragma unroll
            for (int q = 0; q < 10; q++) {
                int n = base + q;
                g_rowptr[n] = excl; g_cursor[n] = excl; excl += loc[q];
                int d = g_deg[n];
                g_dis[n] = (d > 0) ? (1.0f / sqrtf((float)d)) : 0.0f;
            }
        }
        if (tid == 1023) g_rowptr[NNODE] = wsum[31];
    } else {
        unsigned nw = (gridDim.x - 1) * 32u;
        unsigned w  = (blockIdx.x - 1) * 32u + (threadIdx.x >> 5);
        fill_ncol_p(out, np0, np1, w, nw, threadIdx.x & 31u);
    }
}

__global__ void k_scatter(const int* __restrict__ row, const int* __restrict__ col,
                          float4* __restrict__ out, unsigned alo, unsigned ahi) {
    int b = blockIdx.x;
    if (b < NEDGE / 256) {
        int i = b * 256 + threadIdx.x;
        int d = col[i];
        int p = atomicAdd(&g_cursor[d], 1);
        g_src[p] = row[i];
    } else {
        unsigned nt = (gridDim.x - NEDGE / 256) * 256u;
        fill_attr_f(out, alo, ahi, (b - NEDGE / 256) * 256u + threadIdx.x, nt);
    }
}

// block (128 thr) per node: lane=4-col group, slot=edge sub-slot; float4 gather
__global__ void k_score(const float* __restrict__ x, float4* __restrict__ out,
                        unsigned rp0, unsigned rp1) {
    int b = blockIdx.x;
    if (b < NNODE) {
        __shared__ int    s_off[128];
        __shared__ float  s_coef[128];
        __shared__ float4 sred[128];
        int t = threadIdx.x;
        int lane = t & 31, slot = t >> 5;
        int st = g_rowptr[b], en = g_rowptr[b + 1];
        float4 acc = make_float4(0.f, 0.f, 0.f, 0.f);
        for (int base = st; base < en; base += 128) {
            __syncthreads();
            int idx = base + t;
            if (idx < en) {
                int s = g_src[idx];
                s_off[t] = s * CCH;
                s_coef[t] = g_dis[s];
            }
            __syncthreads();
            int cnt = min(128, en - base);
#pragma unroll 4
            for (int e = slot; e < cnt; e += 4) {
                float cf = s_coef[e];
                float4 xv = *(const float4*)(x + s_off[e] + lane * 4);
                acc.x += cf * xv.x; acc.y += cf * xv.y;
                acc.z += cf * xv.z; acc.w += cf * xv.w;
            }
        }
        sred[t] = acc;
        __syncthreads();
        if (t < 64) {
            float4 o = sred[t + 64];
            sred[t].x += o.x; sred[t].y += o.y; sred[t].z += o.z; sred[t].w += o.w;
        }
        __syncthreads();
        if (t < 32) {
            float4 a = sred[t], o = sred[t + 32];
            a.x += o.x; a.y += o.y; a.z += o.z; a.w += o.w;
            float4 xj = ((const float4*)(x + b * CCH))[t];
            float dj = g_dis[b];
            float v = fabsf(xj.x - dj * a.x) + fabsf(xj.y - dj * a.y)
                    + fabsf(xj.z - dj * a.z) + fabsf(xj.w - dj * a.w);
#pragma unroll
            for (int o2 = 16; o2; o2 >>= 1) v += __shfl_xor_sync(0xFFFFFFFFu, v, o2);
            if (t == 0) g_s[b] = tanhf(v * g_a);
        }
    } else {
        unsigned nw = (gridDim.x - NNODE) * 4u;
        unsigned w  = (b - NNODE) * 4u + (threadIdx.x >> 5);
        fill_nrow_p(out, rp0, rp1, w, nw, threadIdx.x & 31u);
    }
}

// stable top-k via exact ranking: 5 blocks per graph, key=(flip(s)<<32 | rev idx)
#define RANK_BLOCKS (NGR * 5)
__global__ void k_rank(float4* __restrict__ out, unsigned np0, unsigned np1) {
    int b = blockIdx.x;
    if (b < RANK_BLOCKS) {
        __shared__ unsigned long long key[NPER];
        int g = b / 5, part = b % 5;
        int tid = threadIdx.x;
        for (int i = tid; i < NPER; i += 256) {
            unsigned u = __float_as_uint(g_s[g * NPER + i]);
            u ^= (u & 0x80000000u) ? 0xFFFFFFFFu : 0x80000000u;   // order-preserving
            key[i] = (((unsigned long long)u) << 32) | (unsigned)(NPER - 1 - i);
        }
        __syncthreads();
        int i0 = part * 250 + tid;
        if (tid < 250) {
            unsigned long long myk = key[i0];
            int rank = 0;
#pragma unroll 5
            for (int j = 0; j < NPER; j++) rank += (key[j] > myk);
            if (rank < KTOP) g_perm[g * KTOP + rank] = g * NPER + i0;
        }
    } else {
        unsigned nw = (gridDim.x - RANK_BLOCKS) * 8u;
        unsigned w  = (b - RANK_BLOCKS) * 8u + (threadIdx.x >> 5);
        fill_ncol_p(out, np0, np1, w, nw, threadIdx.x & 31u);
    }
}

// x_p gather (256000 f4) + batch tail (2000 f4)
__global__ void k_final(const float* __restrict__ x, float4* __restrict__ out) {
    unsigned j = blockIdx.x * 256u + threadIdx.x;
    if (j < 256000u) {
        unsigned i = j >> 5;                    // pooled row
        int p = g_perm[i];
        float s = g_s[p];
        float4 xv = ((const float4*)(x + p * CCH))[j & 31u];
        out[R_XP + j] = make_float4(xv.x * s, xv.y * s, xv.z * s, xv.w * s);
    } else if (j < 258000u) {
        unsigned r = j - 256000u;
        float f = (float)(r / 250u);
        out[R_BATCH + r] = make_float4(f, f, f, f);
    }
}

// ---------------- scalar fallback (out_size != TOTAL) ---------------------------
__device__ __forceinline__ float out_value1(int t, const float* __restrict__ x) {
    if (t < OFF1) {
        int i = t >> 7, c = t & 127;
        int p = g_perm[i];
        return x[p * CCH + c] * g_s[p];
    } else if (t < OFF2) return (float)((t - OFF1) / KTOP);
    else if (t < OFF3) {
        int u = t - OFF2;
        return (float)((u / (KTOP * KTOP)) * KTOP + u % KTOP);
    } else if (t < OFF4) return 1.0f;
    else if (t < TOTAL) return (float)((t - OFF4) / KTOP);
    return 0.0f;
}
__global__ void k_out1(const float* __restrict__ x, float* __restrict__ out, int n) {
    int j = blockIdx.x * blockDim.x + threadIdx.x;
    if (j < n) out[j] = out_value1(j, x);
}

// ---------------- launch ---------------------------------------------------------
extern "C" void kernel_launch(void* const* d_in, const int* in_sizes, int n_in,
                              void* d_out, int out_size) {
    const float* x  = (const float*)d_in[0];
    const int*   ei = (const int*)d_in[1];
    const float* w  = (const float*)d_in[4];
    float4* out = (float4*)d_out;

    const int* row = ei;
    const int* col = ei + NEDGE;

    if (out_size == TOTAL) {
        // attr f4 region [4256000, 6256000): init 300K, deg 850K, scatter 850K
        // ncol periods [0,8000): scan [0,4000), rank [4000,8000)
        // nrow periods [0,8000): score
        k_init   <<<40 + 512,          256>>>(w, out, R_ATTR, R_ATTR + 300000u);
        k_deg    <<<NEDGE/256 + 1024,  256>>>(row, col, out, R_ATTR + 300000u, R_ATTR + 1150000u);
        k_scan   <<<1 + 128,          1024>>>(out, 0u, 4000u);
        k_scatter<<<NEDGE/256 + 1024,  256>>>(row, col, out, R_ATTR + 1150000u, R_ATTR + 2000000u);
        k_score  <<<NNODE + 2048,      128>>>(x, out, 0u, 8000u);
        k_rank   <<<RANK_BLOCKS + 256, 256>>>(out, 4000u, 8000u);
        k_final  <<<(258000 + 255)/256, 256>>>(x, out);
    } else {
        k_init   <<<40,         256>>>(w, out, 0u, 0u);
        k_deg    <<<NEDGE/256,  256>>>(row, col, out, 0u, 0u);
        k_scan   <<<1,         1024>>>(out, 0u, 0u);
        k_scatter<<<NEDGE/256,  256>>>(row, col, out, 0u, 0u);
        k_score  <<<NNODE,      128>>>(x, out, 0u, 0u);
        k_rank   <<<RANK_BLOCKS, 256>>>(out, 0u, 0u);
        k_out1   <<<(out_size + 255)/256, 256>>>(x, (float*)d_out, out_size);
    }
}

// round 4
// speedup vs baseline: 1.1326x; 1.0215x over previous
#include <cuda_runtime.h>
#include <math.h>

// Problem constants
#define NNODE 10000
#define CCH   128
#define NEDGE 320000
#define NGR   8
#define NPER  1250
#define KTOP  1000
#define NK    8000

// element-space layout
#define OFF1  (NK * CCH)                 // 1,024,000
#define E2    (NK * KTOP)                // 8,000,000
#define OFF2  (OFF1 + E2)
#define OFF3  (OFF2 + E2)
#define OFF4  (OFF3 + E2)
#define TOTAL (OFF4 + NK)                // 25,032,000

// float4-space region starts
#define R_XP    0u
#define R_NROW  256000u
#define R_NCOL  2256000u
#define R_ATTR  4256000u
#define R_BATCH 6256000u
#define F_TOTAL 6258000u

// ---------------- scratch -----------------------------------------------------
__device__ int   g_deg[NNODE];
__device__ int   g_cnt[NNODE];
__device__ int   g_rowptr[NNODE + 1];
__device__ int   g_rank[NEDGE];
__device__ int   g_src[NEDGE];
__device__ float g_dis[NNODE];
__device__ float g_s[NNODE];
__device__ int   g_perm[NK];
__device__ float g_a;

// ---------------- division-free warp-period fills ------------------------------
__device__ __forceinline__ void fill_nrow_p(float4* __restrict__ out,
                                            unsigned p0, unsigned p1,
                                            unsigned w, unsigned nw, unsigned lane) {
    for (unsigned p = p0 + w; p < p1; p += nw) {
        float4* base = out + R_NROW + p * 250u;
        float f = (float)p;
        float4 v = make_float4(f, f, f, f);
        for (unsigned i = lane; i < 250u; i += 32u) base[i] = v;
    }
}
__device__ __forceinline__ void fill_ncol_p(float4* __restrict__ out,
                                            unsigned p0, unsigned p1,
                                            unsigned w, unsigned nw, unsigned lane) {
    for (unsigned p = p0 + w; p < p1; p += nw) {
        float4* base = out + R_NCOL + p * 250u;
        float g1000 = (float)((p / 1000u) * 1000u);
        float fb = g1000 + (float)(4u * lane);
        for (unsigned i = lane; i < 250u; i += 32u) {
            base[i] = make_float4(fb, fb + 1.f, fb + 2.f, fb + 3.f);
            fb += 128.f;
        }
    }
}
__device__ __forceinline__ void fill_attr_f(float4* __restrict__ out,
                                            unsigned lo, unsigned hi,
                                            unsigned t, unsigned nt) {
    float4 v = make_float4(1.f, 1.f, 1.f, 1.f);
    for (unsigned j = lo + t; j < hi; j += nt) out[j] = v;
}

// ---------------- kernels ------------------------------------------------------

// degrees (+per-edge rank from atomic return) + g_a; fill: attr region
#define EB (NEDGE / 256)    // 1250 edge blocks
__global__ void k_deg(const int* __restrict__ row, const int* __restrict__ col,
                      const float* __restrict__ w,
                      float4* __restrict__ out, unsigned alo, unsigned ahi) {
    int b = blockIdx.x;
    if (b < EB) {
        int i = b * 256 + threadIdx.x;
        atomicAdd(&g_deg[row[i]], 1);
        g_rank[i] = atomicAdd(&g_cnt[col[i]], 1);
        if (b == 0 && threadIdx.x < 32) {
            float sw = 0.f, sw2 = 0.f;
            for (int c = threadIdx.x; c < CCH; c += 32) {
                float v = w[c]; sw += v; sw2 += v * v;
            }
            for (int o = 16; o; o >>= 1) {
                sw  += __shfl_xor_sync(0xFFFFFFFFu, sw, o);
                sw2 += __shfl_xor_sync(0xFFFFFFFFu, sw2, o);
            }
            if (threadIdx.x == 0) g_a = sw / sqrtf(sw2);
        }
    } else {
        unsigned nt = (gridDim.x - EB) * 256u;
        fill_attr_f(out, alo, ahi, (b - EB) * 256u + threadIdx.x, nt);
    }
}

// block 0: single-pass scan of cnt -> rowptr + dis; fill: ncol periods
__global__ void k_scan(float4* __restrict__ out, unsigned np0, unsigned np1) {
    if (blockIdx.x == 0) {
        int tid = threadIdx.x;
        int base = tid * 10;
        int loc[10];
        int sum = 0;
        bool act = (base < NNODE);
        if (act) {
#pragma unroll
            for (int q = 0; q < 10; q++) { int v = g_cnt[base + q]; loc[q] = v; sum += v; }
        }
        int lane = tid & 31, wid = tid >> 5;
        int val = sum;
#pragma unroll
        for (int o = 1; o < 32; o <<= 1) {
            int n = __shfl_up_sync(0xFFFFFFFFu, val, o);
            if (lane >= o) val += n;
        }
        __shared__ int wsum[32];
        if (lane == 31) wsum[wid] = val;
        __syncthreads();
        if (wid == 0) {
            int v2 = wsum[lane];
#pragma unroll
            for (int o = 1; o < 32; o <<= 1) {
                int n = __shfl_up_sync(0xFFFFFFFFu, v2, o);
                if (lane >= o) v2 += n;
            }
            wsum[lane] = v2;
        }
        __syncthreads();
        int excl = val - sum + (wid > 0 ? wsum[wid - 1] : 0);
        if (act) {
#pragma unroll
            for (int q = 0; q < 10; q++) {
                int n = base + q;
                g_rowptr[n] = excl; excl += loc[q];
                int d = g_deg[n];
                g_dis[n] = (d > 0) ? (1.0f / sqrtf((float)d)) : 0.0f;
            }
        }
        if (tid == 1023) g_rowptr[NNODE] = wsum[31];
    } else {
        unsigned nw = (gridDim.x - 1) * 32u;
        unsigned w  = (blockIdx.x - 1) * 32u + (threadIdx.x >> 5);
        fill_ncol_p(out, np0, np1, w, nw, threadIdx.x & 31u);
    }
}

// atomic-free CSR scatter; fill: ncol periods
__global__ void k_scatter(const int* __restrict__ row, const int* __restrict__ col,
                          float4* __restrict__ out, unsigned np0, unsigned np1) {
    int b = blockIdx.x;
    if (b < EB) {
        int i = b * 256 + threadIdx.x;
        int d = col[i];
        g_src[g_rowptr[d] + g_rank[i]] = row[i];
    } else {
        unsigned nw = (gridDim.x - EB) * 8u;
        unsigned w  = (b - EB) * 8u + (threadIdx.x >> 5);
        fill_ncol_p(out, np0, np1, w, nw, threadIdx.x & 31u);
    }
}

// block (128 thr) per node: lane=4-col group, slot=edge sub-slot; float4 gather
__global__ void k_score(const float* __restrict__ x, float4* __restrict__ out,
                        unsigned rp0, unsigned rp1) {
    int b = blockIdx.x;
    if (b < NNODE) {
        __shared__ int    s_off[128];
        __shared__ float  s_coef[128];
        __shared__ float4 sred[128];
        int t = threadIdx.x;
        int lane = t & 31, slot = t >> 5;
        int st = g_rowptr[b], en = g_rowptr[b + 1];
        float4 acc = make_float4(0.f, 0.f, 0.f, 0.f);
        for (int base = st; base < en; base += 128) {
            __syncthreads();
            int idx = base + t;
            if (idx < en) {
                int s = g_src[idx];
                s_off[t] = s * CCH;
                s_coef[t] = g_dis[s];
            }
            __syncthreads();
            int cnt = min(128, en - base);
#pragma unroll 4
            for (int e = slot; e < cnt; e += 4) {
                float cf = s_coef[e];
                float4 xv = *(const float4*)(x + s_off[e] + lane * 4);
                acc.x += cf * xv.x; acc.y += cf * xv.y;
                acc.z += cf * xv.z; acc.w += cf * xv.w;
            }
        }
        sred[t] = acc;
        __syncthreads();
        if (t < 64) {
            float4 o = sred[t + 64];
            sred[t].x += o.x; sred[t].y += o.y; sred[t].z += o.z; sred[t].w += o.w;
        }
        __syncthreads();
        if (t < 32) {
            float4 a = sred[t], o = sred[t + 32];
            a.x += o.x; a.y += o.y; a.z += o.z; a.w += o.w;
            float4 xj = ((const float4*)(x + b * CCH))[t];
            float dj = g_dis[b];
            float v = fabsf(xj.x - dj * a.x) + fabsf(xj.y - dj * a.y)
                    + fabsf(xj.z - dj * a.z) + fabsf(xj.w - dj * a.w);
#pragma unroll
            for (int o2 = 16; o2; o2 >>= 1) v += __shfl_xor_sync(0xFFFFFFFFu, v, o2);
            if (t == 0) g_s[b] = tanhf(v * g_a);
        }
    } else {
        unsigned nw = (gridDim.x - NNODE) * 4u;
        unsigned w  = (b - NNODE) * 4u + (threadIdx.x >> 5);
        fill_nrow_p(out, rp0, rp1, w, nw, threadIdx.x & 31u);
    }
}

// stable top-k ranking + x_p write + batch tail + counter re-zero for next run.
#define RANK_BLOCKS (NGR * 5)
__global__ void k_rank(const float* __restrict__ x, float4* __restrict__ out,
                       unsigned np0, unsigned np1) {
    int b = blockIdx.x;
    if (b < RANK_BLOCKS) {
        __shared__ unsigned long long key[NPER];
        __shared__ float sval[NPER];
        int g = b / 5, part = b % 5;
        int tid = threadIdx.x;
        for (int i = tid; i < NPER; i += 256) {
            float s = g_s[g * NPER + i];
            sval[i] = s;
            unsigned u = __float_as_uint(s);
            u ^= (u & 0x80000000u) ? 0xFFFFFFFFu : 0x80000000u;   // order-preserving
            key[i] = (((unsigned long long)u) << 32) | (unsigned)(NPER - 1 - i);
        }
        __syncthreads();
        int i0 = part * 250 + tid;
        if (tid < 250) {
            unsigned long long myk = key[i0];
            int rank = 0;
#pragma unroll 5
            for (int j = 0; j < NPER; j++) rank += (key[j] > myk);
            if (rank < KTOP) {
                int node = g * NPER + i0;
                g_perm[g * KTOP + rank] = node;                 // fallback path
                float s = sval[i0];
                const float4* xr = (const float4*)(x + node * CCH);
                float4* dst = out + R_XP + (unsigned)(g * KTOP + rank) * 32u;
#pragma unroll
                for (int c = 0; c < 32; c++) {
                    float4 xv = xr[c];
                    dst[c] = make_float4(xv.x * s, xv.y * s, xv.z * s, xv.w * s);
                }
            }
        }
    } else {
        int zb = b - RANK_BLOCKS;
        // re-zero counters for the next graph replay
        int zi = zb * 256 + threadIdx.x;
        if (zi < NNODE) { g_deg[zi] = 0; g_cnt[zi] = 0; }
        // batch tail: region period zb has constant value zb
        if (zb < NGR && threadIdx.x < 250) {
            float f = (float)zb;
            out[R_BATCH + zb * 250u + threadIdx.x] = make_float4(f, f, f, f);
        }
        unsigned nw = (gridDim.x - RANK_BLOCKS) * 8u;
        unsigned w  = (unsigned)zb * 8u + (threadIdx.x >> 5);
        fill_ncol_p(out, np0, np1, w, nw, threadIdx.x & 31u);
    }
}

// ---------------- scalar fallback (out_size != TOTAL) ---------------------------
__device__ __forceinline__ float out_value1(int t, const float* __restrict__ x) {
    if (t < OFF1) {
        int i = t >> 7, c = t & 127;
        int p = g_perm[i];
        return x[p * CCH + c] * g_s[p];
    } else if (t < OFF2) return (float)((t - OFF1) / KTOP);
    else if (t < OFF3) {
        int u = t - OFF2;
        return (float)((u / (KTOP * KTOP)) * KTOP + u % KTOP);
    } else if (t < OFF4) return 1.0f;
    else if (t < TOTAL) return (float)((t - OFF4) / KTOP);
    return 0.0f;
}
__global__ void k_out1(const float* __restrict__ x, float* __restrict__ out, int n) {
    int j = blockIdx.x * blockDim.x + threadIdx.x;
    if (j < n) out[j] = out_value1(j, x);
}
__global__ void k_zero() {
    int i = blockIdx.x * blockDim.x + threadIdx.x;
    if (i < NNODE) { g_deg[i] = 0; g_cnt[i] = 0; }
}

// ---------------- launch ---------------------------------------------------------
extern "C" void kernel_launch(void* const* d_in, const int* in_sizes, int n_in,
                              void* d_out, int out_size) {
    const float* x  = (const float*)d_in[0];
    const int*   ei = (const int*)d_in[1];
    const float* w  = (const float*)d_in[4];
    float4* out = (float4*)d_out;

    const int* row = ei;
    const int* col = ei + NEDGE;

    if (out_size == TOTAL) {
        // attr region (32 MB) -> deg; ncol periods: scan [0,1500), scatter [1500,4000),
        // rank [4000,8000); nrow periods [0,8000) -> score; batch+x_p -> rank.
        k_deg    <<<EB + 2048,         256>>>(row, col, w, out, R_ATTR, R_ATTR + 2000000u);
        k_scan   <<<1 + 128,          1024>>>(out, 0u, 1500u);
        k_scatter<<<EB + 1024,         256>>>(row, col, out, 1500u, 4000u);
        k_score  <<<NNODE + 2048,      128>>>(x, out, 0u, 8000u);
        k_rank   <<<RANK_BLOCKS + 1024, 256>>>(x, out, 4000u, 8000u);
    } else {
        k_zero   <<<40,         256>>>();
        k_deg    <<<EB,         256>>>(row, col, w, out, 0u, 0u);
        k_scan   <<<1,         1024>>>(out, 0u, 0u);
        k_scatter<<<EB,         256>>>(row, col, out, 0u, 0u);
        k_score  <<<NNODE,      128>>>(x, out, 0u, 0u);
        k_rank   <<<RANK_BLOCKS, 256>>>(x, out, 0u, 0u);
        k_out1   <<<(out_size + 255)/256, 256>>>(x, (float*)d_out, out_size);
    }
}